// round 15
// baseline (speedup 1.0000x reference)
#include <cuda_runtime.h>
#include <cuda_fp16.h>
#include <cstdint>

typedef unsigned long long ull;

// ---------------- static scratch (no allocations allowed) ----------------
__device__ float g_Wf[4][80][64];          // folded weights: [stage][o<8:q,8..15:k,16..79:v][c]
__device__ float g_bf[4][80];              // folded biases
__device__ __half g_q[4][8 * 8192];        // [st][ b*8P + p*8 + c ]  POINT-major, scaled, f16
__device__ __half g_k[4][8 * 8192];        // [st][ b*8P + p*8 + c ]  point-major, f16
__device__ __half g_v[4][64 * 8192];       // [st][ b*64P + c*P + p ] channel-major, f16
__device__ float g_accp[10 * 8192][64];    // split-K partial numerators (stages 0,1 only)
__device__ float g_denp[10 * 8192];        // split-K partial denominators
__device__ float g_ctx[8192 * 256];        // [pos][st*64+c] (only stages 2,3 written/read)

// ---------------- helpers ----------------
__device__ __forceinline__ float ex2(float x) {
    float y;
    asm("ex2.approx.f32 %0, %1;" : "=f"(y) : "f"(x));
    return y;
}
__device__ __forceinline__ float tf32r(float x) {
    uint32_t u;
    asm("cvt.rna.tf32.f32 %0, %1;" : "=r"(u) : "f"(x));
    return __uint_as_float(u);
}
__device__ __forceinline__ uint32_t packh2(float lo, float hi) {
    uint32_t d;
    asm("cvt.rn.f16x2.f32 %0, %1, %2;" : "=r"(d) : "f"(hi), "f"(lo));
    return d;
}

// tf32 MMA (conv): D(16x8) += A(16x8,row) * B(8x8,col)
__device__ __forceinline__ void mma16n8k8(float* d, const uint32_t* a, uint32_t b0, uint32_t b1) {
    asm volatile(
        "mma.sync.aligned.m16n8k8.row.col.f32.tf32.tf32.f32 "
        "{%0,%1,%2,%3}, {%4,%5,%6,%7}, {%8,%9}, {%0,%1,%2,%3};"
        : "+f"(d[0]), "+f"(d[1]), "+f"(d[2]), "+f"(d[3])
        : "r"(a[0]), "r"(a[1]), "r"(a[2]), "r"(a[3]), "r"(b0), "r"(b1));
}
// f16 MMA k=8
__device__ __forceinline__ void mma_h808(float* d, uint32_t a0, uint32_t a1, uint32_t b0) {
    asm volatile(
        "mma.sync.aligned.m16n8k8.row.col.f32.f16.f16.f32 "
        "{%0,%1,%2,%3}, {%4,%5}, {%6}, {%0,%1,%2,%3};"
        : "+f"(d[0]), "+f"(d[1]), "+f"(d[2]), "+f"(d[3])
        : "r"(a0), "r"(a1), "r"(b0));
}
// f16 MMA k=16
__device__ __forceinline__ void mma_h16816(float* d, uint32_t a0, uint32_t a1, uint32_t a2,
                                           uint32_t a3, uint32_t b0, uint32_t b1) {
    asm volatile(
        "mma.sync.aligned.m16n8k16.row.col.f32.f16.f16.f32 "
        "{%0,%1,%2,%3}, {%4,%5,%6,%7}, {%8,%9}, {%0,%1,%2,%3};"
        : "+f"(d[0]), "+f"(d[1]), "+f"(d[2]), "+f"(d[3])
        : "r"(a0), "r"(a1), "r"(a2), "r"(a3), "r"(b0), "r"(b1));
}

// ---------------- 1. fold BN affine + softmax scale into weights ----------------
__global__ void fold_kernel(const float* __restrict__ Wq, const float* __restrict__ bq,
                            const float* __restrict__ gq, const float* __restrict__ beq,
                            const float* __restrict__ Wk, const float* __restrict__ bk,
                            const float* __restrict__ gk, const float* __restrict__ bek,
                            const float* __restrict__ Wv, const float* __restrict__ bv) {
    int st = blockIdx.x, o = threadIdx.x;
    const float SCALE = 0.35355339059327373f * 1.4426950408889634f;  // kc^-0.5 * log2e
    if (o < 8) {
        float g = gq[st * 8 + o];
        for (int c = 0; c < 64; c++)
            g_Wf[st][o][c] = g * Wq[(st * 8 + o) * 64 + c] * SCALE;
        g_bf[st][o] = (g * bq[st * 8 + o] + beq[st * 8 + o]) * SCALE;
    } else if (o < 16) {
        int i = o - 8;
        float g = gk[st * 8 + i];
        for (int c = 0; c < 64; c++)
            g_Wf[st][o][c] = g * Wk[(st * 8 + i) * 64 + c];
        g_bf[st][o] = g * bk[st * 8 + i] + bek[st * 8 + i];
    } else {
        int i = o - 16;
        for (int c = 0; c < 64; c++)
            g_Wf[st][o][c] = Wv[(st * 64 + i) * 64 + c];
        g_bf[st][o] = bv[st * 64 + i];
    }
}

// ---------------- 2. projections: one stage per CTA (grid 64 x 4), f16 outputs --------
__global__ void __launch_bounds__(128) proj_kernel(const float* __restrict__ x1,
                                                   const float* __restrict__ x2) {
    __shared__ __align__(16) float sW[80][64];
    __shared__ float sb[80];
    int t = threadIdx.x;
    int st = blockIdx.y;

    {
        const float4* src = (const float4*)g_Wf[st];
        float4* dst = (float4*)sW;
#pragma unroll
        for (int i = 0; i < 10; i++) dst[i * 128 + t] = src[i * 128 + t];
        if (t < 80) sb[t] = g_bf[st][t];
    }
    __syncthreads();

    int pos = blockIdx.x * 128 + t;
    int h = pos >> 7, w2 = pos & 127;
    int w = w2 & 63, hv = w2 >> 6;
    const float* xsrc = hv ? x2 : x1;

    float4 xreg[16];
#pragma unroll
    for (int c = 0; c < 16; c++) {
        float4 v;
        v.x = xsrc[(4 * c + 0) * 4096 + h * 64 + w];
        v.y = xsrc[(4 * c + 1) * 4096 + h * 64 + w];
        v.z = xsrc[(4 * c + 2) * 4096 + h * 64 + w];
        v.w = xsrc[(4 * c + 3) * 4096 + h * 64 + w];
        xreg[c] = v;
    }

    int shift = 6 - st;
    int P = 8192 >> (2 * st);
    int m = (1 << shift) - 1;
    int si = h >> shift, hi = h & m;
    int sj = w >> shift, wi = w & m;
    int b = (si << st) + sj;
    int p = (((hi << shift) + wi) << 1) | hv;

    __half* qdst = g_q[st] + b * (8 * P) + p * 8;
    __half* kdst = g_k[st] + b * (8 * P) + p * 8;
#pragma unroll
    for (int o = 0; o < 8; o++) {
        float aq = sb[o], ak = sb[8 + o];
#pragma unroll
        for (int c = 0; c < 16; c++) {
            float4 xv = xreg[c];
            float4 wq = *(const float4*)&sW[o][4 * c];
            float4 wk = *(const float4*)&sW[8 + o][4 * c];
            aq += wq.x * xv.x + wq.y * xv.y + wq.z * xv.z + wq.w * xv.w;
            ak += wk.x * xv.x + wk.y * xv.y + wk.z * xv.z + wk.w * xv.w;
        }
        qdst[o] = __float2half_rn(aq);
        kdst[o] = __float2half_rn(ak);
    }
    __half* vdst = g_v[st] + b * (64 * P) + p;
#pragma unroll 4
    for (int o = 0; o < 64; o += 4) {
        float a0 = sb[16 + o], a1 = sb[17 + o], a2 = sb[18 + o], a3 = sb[19 + o];
#pragma unroll
        for (int c = 0; c < 16; c++) {
            float4 xv = xreg[c];
            float4 w0 = *(const float4*)&sW[16 + o][4 * c];
            float4 w1 = *(const float4*)&sW[17 + o][4 * c];
            float4 w2v = *(const float4*)&sW[18 + o][4 * c];
            float4 w3 = *(const float4*)&sW[19 + o][4 * c];
            a0 += w0.x * xv.x + w0.y * xv.y + w0.z * xv.z + w0.w * xv.w;
            a1 += w1.x * xv.x + w1.y * xv.y + w1.z * xv.z + w1.w * xv.w;
            a2 += w2v.x * xv.x + w2v.y * xv.y + w2v.z * xv.z + w2v.w * xv.w;
            a3 += w3.x * xv.x + w3.y * xv.y + w3.z * xv.z + w3.w * xv.w;
        }
        vdst[(o + 0) * P] = __float2half_rn(a0);
        vdst[(o + 1) * P] = __float2half_rn(a1);
        vdst[(o + 2) * P] = __float2half_rn(a2);
        vdst[(o + 3) * P] = __float2half_rn(a3);
    }
}

// ---------------- 3. flash attention: fp16 tensor-core, 64-key staging ----------
// grid = 768 CTAs: st0: 512 (qt64 x ks8), st1: 128 (b4 x qt16 x ks2), st2: 64, st3: 64
__global__ void __launch_bounds__(128, 4) flash_kernel() {
    __shared__ __half Vs[2][64][72];   // V tile [c][k], 64 keys, pitch 72 halves
    __shared__ __half Kt[2][64][8];    // K tile [key][ch]

    int bid = blockIdx.x, t = threadIdx.x;
    int st, local, KS, poff;
    if (bid < 512)      { st = 0; local = bid;       KS = 8; poff = 0; }
    else if (bid < 640) { st = 1; local = bid - 512; KS = 2; poff = 8 * 8192; }
    else if (bid < 704) { st = 2; local = bid - 640; KS = 1; poff = 0; }
    else                { st = 3; local = bid - 704; KS = 1; poff = 0; }
    int P = 8192 >> (2 * st);
    int QT = P >> 7;
    int ks = local % KS; local /= KS;
    int qt = local % QT;
    int b = local / QT;
    int Klen = P / KS;
    int k0 = ks * Klen;

    const __half* qbase = g_q[st] + b * (8 * P);
    const __half* kbase = g_k[st] + b * (8 * P);
    const __half* vbase = g_v[st] + b * (64 * P);

    int w = t >> 5, lane = t & 31;
    int g = lane >> 2, r = lane & 3;

    // persistent Q A-fragments (f16, k=8)
    uint32_t qf[2][2];
#pragma unroll
    for (int mt = 0; mt < 2; mt++) {
        int row = qt * 128 + w * 32 + mt * 16;
        qf[mt][0] = *(const uint32_t*)&qbase[(row + g) * 8 + 2 * r];
        qf[mt][1] = *(const uint32_t*)&qbase[(row + g + 8) * 8 + 2 * r];
    }

    float acc[2][8][4];
#pragma unroll
    for (int mt = 0; mt < 2; mt++)
#pragma unroll
        for (int nt = 0; nt < 8; nt++)
#pragma unroll
            for (int i = 0; i < 4; i++) acc[mt][nt][i] = 0.f;
    float den4[2][2] = {{0.f, 0.f}, {0.f, 0.f}};

    auto stage = [&](int kt, int bi) {
        if (kt < Klen) {
            if (t < 64) {
                *(float4*)&Kt[bi][t][0] = *(const float4*)&kbase[(k0 + kt + t) * 8];
            }
#pragma unroll
            for (int i = 0; i < 4; i++) {
                int idx = t + i * 128;          // 512 chunks of 8 halves (64c x 8chunks)
                int c = idx >> 3, j8 = idx & 7;
                *(float4*)&Vs[bi][c][j8 * 8] =
                    *(const float4*)&vbase[c * P + k0 + kt + j8 * 8];
            }
        }
    };

    stage(0, 0);
    __syncthreads();

    int nb = Klen >> 6;
    for (int n = 0; n < nb; n++) {
        int cur = n & 1, nxt = cur ^ 1;
        stage((n + 1) << 6, nxt);   // overlaps both halves' MMA phases

#pragma unroll
        for (int hk = 0; hk < 2; hk++) {
            int kb0 = hk * 32;
            // phase 1: QK via f16 MMA -> exp -> f16x2 A-fragments (registers only)
            uint32_t eh[2][4][2];
#pragma unroll
            for (int nt = 0; nt < 4; nt++) {
                uint32_t kb = *(const uint32_t*)&Kt[cur][kb0 + nt * 8 + g][2 * r];
                float sc0[4] = {0.f, 0.f, 0.f, 0.f};
                float sc1[4] = {0.f, 0.f, 0.f, 0.f};
                mma_h808(sc0, qf[0][0], qf[0][1], kb);
                mma_h808(sc1, qf[1][0], qf[1][1], kb);
                float e00 = ex2(sc0[0]), e01 = ex2(sc0[1]), e02 = ex2(sc0[2]), e03 = ex2(sc0[3]);
                den4[0][0] += e00 + e01;
                den4[0][1] += e02 + e03;
                eh[0][nt][0] = packh2(e00, e01);
                eh[0][nt][1] = packh2(e02, e03);
                float e10 = ex2(sc1[0]), e11 = ex2(sc1[1]), e12 = ex2(sc1[2]), e13 = ex2(sc1[3]);
                den4[1][0] += e10 + e11;
                den4[1][1] += e12 + e13;
                eh[1][nt][0] = packh2(e10, e11);
                eh[1][nt][1] = packh2(e12, e13);
            }
            // phase 2: EV via f16 m16n8k16
#pragma unroll
            for (int k16 = 0; k16 < 2; k16++) {
#pragma unroll
                for (int nt = 0; nt < 8; nt++) {
                    uint32_t b0 = *(const uint32_t*)&Vs[cur][nt * 8 + g][kb0 + 16 * k16 + 2 * r];
                    uint32_t b1 = *(const uint32_t*)&Vs[cur][nt * 8 + g][kb0 + 16 * k16 + 8 + 2 * r];
                    mma_h16816(acc[0][nt], eh[0][2 * k16][0], eh[0][2 * k16][1],
                               eh[0][2 * k16 + 1][0], eh[0][2 * k16 + 1][1], b0, b1);
                    mma_h16816(acc[1][nt], eh[1][2 * k16][0], eh[1][2 * k16][1],
                               eh[1][2 * k16 + 1][0], eh[1][2 * k16 + 1][1], b0, b1);
                }
            }
        }
        __syncthreads();   // one barrier per 64 keys
    }

    // reduce den across the 4 lanes sharing a row
#pragma unroll
    for (int mt = 0; mt < 2; mt++)
#pragma unroll
        for (int rr = 0; rr < 2; rr++) {
            float d = den4[mt][rr];
            d += __shfl_xor_sync(0xFFFFFFFFu, d, 1);
            d += __shfl_xor_sync(0xFFFFFFFFu, d, 2);
            den4[mt][rr] = d;
        }

    if (KS > 1) {
#pragma unroll
        for (int mt = 0; mt < 2; mt++)
#pragma unroll
            for (int rr = 0; rr < 2; rr++) {
                int qrow = w * 32 + mt * 16 + g + rr * 8;
                int row = poff + ks * 8192 + b * P + qt * 128 + qrow;
                if (r == 0) g_denp[row] = den4[mt][rr];
#pragma unroll
                for (int nt = 0; nt < 8; nt++) {
                    float2 v;
                    v.x = acc[mt][nt][2 * rr];
                    v.y = acc[mt][nt][2 * rr + 1];
                    *(float2*)&g_accp[row][nt * 8 + 2 * r] = v;
                }
            }
    } else {
        int shift = 6 - st;
        int si = b >> st, sj = b & ((1 << st) - 1);
#pragma unroll
        for (int mt = 0; mt < 2; mt++)
#pragma unroll
            for (int rr = 0; rr < 2; rr++) {
                int qrow = w * 32 + mt * 16 + g + rr * 8;
                int p = qt * 128 + qrow;
                float inv = 1.0f / den4[mt][rr];
                int hv = p & 1, tt2 = p >> 1;
                int hi = tt2 >> shift, wi = tt2 & ((1 << shift) - 1);
                int h = (si << shift) + hi;
                int w2 = (sj << shift) + wi + (hv << 6);
                int pos = (h << 7) + w2;
                float* dstp = g_ctx + pos * 256 + st * 64;
#pragma unroll
                for (int nt = 0; nt < 8; nt++) {
                    float2 v;
                    v.x = acc[mt][nt][2 * rr] * inv;
                    v.y = acc[mt][nt][2 * rr + 1] * inv;
                    *(float2*)(dstp + nt * 8 + 2 * r) = v;
                }
            }
    }
}

// ---------------- 4. final 1x1 conv via tf32 MMA with FUSED split-K reduce ------
// out[64 x 8192] = Wo[64 x 256] * ctx^T, where ctx channels 0..127 come from
// summing split-K partials (stages 0,1) and 128..255 from g_ctx (stages 2,3).
__global__ void __launch_bounds__(128) conv_kernel(const float* __restrict__ Wo,
                                                   float* __restrict__ out) {
    __shared__ float As[64][36];   // ctx tile [pos][k]
    __shared__ float Bs[64][36];   // Wo tile  [o][k]
    __shared__ float invs[2][64];
    __shared__ int rows[2][64];
    int t = threadIdx.x;
    int pos0 = blockIdx.x * 64;
    int w = t >> 5, lane = t & 31;
    int g = lane >> 2, r = lane & 3;

    // precompute inverse scatter index + 1/den for stages 0,1 (thread t: stage t>>6, pos a=t&63)
    {
        int stp = t >> 6;
        int a = t & 63;
        int pos = pos0 + a;
        int h = pos >> 7, w2 = pos & 127;
        int hv = w2 >> 6, ww = w2 & 63;
        int shift = 6 - stp;
        int m = (1 << shift) - 1;
        int si = h >> shift, hi = h & m;
        int sj = ww >> shift, wi = ww & m;
        int bb = (si << stp) + sj;
        int p = (((hi << shift) + wi) << 1) | hv;
        int P = 8192 >> (2 * stp);
        int poff = stp ? 8 * 8192 : 0;
        int row = poff + bb * P + p;
        int KSl = stp ? 2 : 8;
        float den = 0.f;
        for (int ksp = 0; ksp < KSl; ksp++) den += g_denp[row + ksp * 8192];
        rows[stp][a] = row;
        invs[stp][a] = 1.0f / den;
    }
    __syncthreads();

    float acc[4][2][4];
#pragma unroll
    for (int mt = 0; mt < 4; mt++)
#pragma unroll
        for (int nt = 0; nt < 2; nt++)
#pragma unroll
            for (int i = 0; i < 4; i++) acc[mt][nt][i] = 0.f;

    for (int ci0 = 0; ci0 < 256; ci0 += 32) {
        int stg = ci0 >> 6;   // 0..3
        __syncthreads();
#pragma unroll
        for (int i = 0; i < 4; i++) {
            int idx = t + i * 128;
            int a = idx >> 3, j8 = idx & 7;
            float4 v;
            if (stg == 0) {
                int row = rows[0][a];
                int cc = (ci0 & 63) + j8 * 4;
                v = make_float4(0.f, 0.f, 0.f, 0.f);
#pragma unroll
                for (int ksp = 0; ksp < 8; ksp++) {
                    float4 x = *(const float4*)&g_accp[row + ksp * 8192][cc];
                    v.x += x.x; v.y += x.y; v.z += x.z; v.w += x.w;
                }
                float inv = invs[0][a];
                v.x *= inv; v.y *= inv; v.z *= inv; v.w *= inv;
            } else if (stg == 1) {
                int row = rows[1][a];
                int cc = (ci0 & 63) + j8 * 4;
                float4 x0 = *(const float4*)&g_accp[row][cc];
                float4 x1 = *(const float4*)&g_accp[row + 8192][cc];
                float inv = invs[1][a];
                v.x = (x0.x + x1.x) * inv;
                v.y = (x0.y + x1.y) * inv;
                v.z = (x0.z + x1.z) * inv;
                v.w = (x0.w + x1.w) * inv;
            } else {
                v = *(const float4*)&g_ctx[(pos0 + a) * 256 + ci0 + j8 * 4];
            }
            v.x = tf32r(v.x); v.y = tf32r(v.y); v.z = tf32r(v.z); v.w = tf32r(v.w);
            *(float4*)&As[a][j8 * 4] = v;
            float4 u = *(const float4*)&Wo[a * 256 + ci0 + j8 * 4];
            u.x = tf32r(u.x); u.y = tf32r(u.y); u.z = tf32r(u.z); u.w = tf32r(u.w);
            *(float4*)&Bs[a][j8 * 4] = u;
        }
        __syncthreads();

#pragma unroll
        for (int ks8 = 0; ks8 < 4; ks8++) {
            int kk = ks8 * 8;
            uint32_t af[4][4];
#pragma unroll
            for (int mt = 0; mt < 4; mt++) {
                int row = mt * 16;
                af[mt][0] = __float_as_uint(Bs[row + g][kk + r]);
                af[mt][1] = __float_as_uint(Bs[row + g + 8][kk + r]);
                af[mt][2] = __float_as_uint(Bs[row + g][kk + r + 4]);
                af[mt][3] = __float_as_uint(Bs[row + g + 8][kk + r + 4]);
            }
#pragma unroll
            for (int nt = 0; nt < 2; nt++) {
                uint32_t b0 = __float_as_uint(As[w * 16 + nt * 8 + g][kk + r]);
                uint32_t b1 = __float_as_uint(As[w * 16 + nt * 8 + g][kk + r + 4]);
#pragma unroll
                for (int mt = 0; mt < 4; mt++) mma16n8k8(acc[mt][nt], af[mt], b0, b1);
            }
        }
    }

#pragma unroll
    for (int mt = 0; mt < 4; mt++)
#pragma unroll
        for (int rr = 0; rr < 2; rr++) {
            int o = mt * 16 + g + rr * 8;
#pragma unroll
            for (int nt = 0; nt < 2; nt++) {
                int pos = pos0 + w * 16 + nt * 8 + 2 * r;
                int h = pos >> 7, w2 = pos & 127;
                int idx = (w2 < 64) ? (o * 4096 + h * 64 + w2)
                                    : (262144 + o * 4096 + h * 64 + (w2 - 64));
                float2 v;
                v.x = acc[mt][nt][2 * rr];
                v.y = acc[mt][nt][2 * rr + 1];
                *(float2*)&out[idx] = v;
            }
        }
}

// ---------------- launch ----------------
extern "C" void kernel_launch(void* const* d_in, const int* in_sizes, int n_in,
                              void* d_out, int out_size) {
    const float* x1 = (const float*)d_in[0];
    const float* x2 = (const float*)d_in[1];
    const float* Wq = (const float*)d_in[2];
    const float* bq = (const float*)d_in[3];
    const float* gq = (const float*)d_in[4];
    const float* beq = (const float*)d_in[5];
    const float* Wk = (const float*)d_in[6];
    const float* bk = (const float*)d_in[7];
    const float* gk = (const float*)d_in[8];
    const float* bek = (const float*)d_in[9];
    const float* Wv = (const float*)d_in[10];
    const float* bv = (const float*)d_in[11];
    const float* Wo = (const float*)d_in[12];
    float* out = (float*)d_out;

    fold_kernel<<<4, 80>>>(Wq, bq, gq, beq, Wk, bk, gk, bek, Wv, bv);
    proj_kernel<<<dim3(64, 4), 128>>>(x1, x2);
    flash_kernel<<<768, 128>>>();
    conv_kernel<<<128, 128>>>(Wo, out);
}

// round 16
// speedup vs baseline: 1.4356x; 1.4356x over previous
#include <cuda_runtime.h>
#include <cuda_fp16.h>
#include <cstdint>

typedef unsigned long long ull;

// ---------------- static scratch (no allocations allowed) ----------------
__device__ float g_Wf[4][80][64];          // folded weights: [stage][o<8:q,8..15:k,16..79:v][c]
__device__ float g_bf[4][80];              // folded biases
__device__ __half g_q[4][8 * 8192];        // [st][ b*8P + p*8 + c ]  POINT-major, scaled, f16
__device__ __half g_k[4][8 * 8192];        // [st][ b*8P + p*8 + c ]  point-major, f16
__device__ __half g_v[4][64 * 8192];       // [st][ b*64P + c*P + p ] channel-major, f16
__device__ float g_accp[10 * 8192][64];    // split-K partial numerators (stages 0,1 only)
__device__ float g_denp[10 * 8192];        // split-K partial denominators
__device__ float g_ctx[8192 * 256];        // [pos][st*64+c]

// ---------------- helpers ----------------
__device__ __forceinline__ float ex2(float x) {
    float y;
    asm("ex2.approx.f32 %0, %1;" : "=f"(y) : "f"(x));
    return y;
}
__device__ __forceinline__ float tf32r(float x) {
    uint32_t u;
    asm("cvt.rna.tf32.f32 %0, %1;" : "=r"(u) : "f"(x));
    return __uint_as_float(u);
}
// pack two f32 into f16x2: lo = first elem (smaller k), hi = second
__device__ __forceinline__ uint32_t packh2(float lo, float hi) {
    uint32_t d;
    asm("cvt.rn.f16x2.f32 %0, %1, %2;" : "=r"(d) : "f"(hi), "f"(lo));
    return d;
}

// tf32 MMA (conv): D(16x8) += A(16x8,row) * B(8x8,col)
__device__ __forceinline__ void mma16n8k8(float* d, const uint32_t* a, uint32_t b0, uint32_t b1) {
    asm volatile(
        "mma.sync.aligned.m16n8k8.row.col.f32.tf32.tf32.f32 "
        "{%0,%1,%2,%3}, {%4,%5,%6,%7}, {%8,%9}, {%0,%1,%2,%3};"
        : "+f"(d[0]), "+f"(d[1]), "+f"(d[2]), "+f"(d[3])
        : "r"(a[0]), "r"(a[1]), "r"(a[2]), "r"(a[3]), "r"(b0), "r"(b1));
}
// f16 MMA k=8: D(16x8) += A(16x8,row,f16) * B(8x8,col,f16)
__device__ __forceinline__ void mma_h808(float* d, uint32_t a0, uint32_t a1, uint32_t b0) {
    asm volatile(
        "mma.sync.aligned.m16n8k8.row.col.f32.f16.f16.f32 "
        "{%0,%1,%2,%3}, {%4,%5}, {%6}, {%0,%1,%2,%3};"
        : "+f"(d[0]), "+f"(d[1]), "+f"(d[2]), "+f"(d[3])
        : "r"(a0), "r"(a1), "r"(b0));
}
// f16 MMA k=16: D(16x8) += A(16x16,row,f16) * B(16x8,col,f16)
__device__ __forceinline__ void mma_h16816(float* d, uint32_t a0, uint32_t a1, uint32_t a2,
                                           uint32_t a3, uint32_t b0, uint32_t b1) {
    asm volatile(
        "mma.sync.aligned.m16n8k16.row.col.f32.f16.f16.f32 "
        "{%0,%1,%2,%3}, {%4,%5,%6,%7}, {%8,%9}, {%0,%1,%2,%3};"
        : "+f"(d[0]), "+f"(d[1]), "+f"(d[2]), "+f"(d[3])
        : "r"(a0), "r"(a1), "r"(a2), "r"(a3), "r"(b0), "r"(b1));
}

// ---------------- 1. fold BN affine + softmax scale into weights ----------------
__global__ void fold_kernel(const float* __restrict__ Wq, const float* __restrict__ bq,
                            const float* __restrict__ gq, const float* __restrict__ beq,
                            const float* __restrict__ Wk, const float* __restrict__ bk,
                            const float* __restrict__ gk, const float* __restrict__ bek,
                            const float* __restrict__ Wv, const float* __restrict__ bv) {
    int st = blockIdx.x, o = threadIdx.x;
    const float SCALE = 0.35355339059327373f * 1.4426950408889634f;  // kc^-0.5 * log2e
    if (o < 8) {
        float g = gq[st * 8 + o];
        for (int c = 0; c < 64; c++)
            g_Wf[st][o][c] = g * Wq[(st * 8 + o) * 64 + c] * SCALE;
        g_bf[st][o] = (g * bq[st * 8 + o] + beq[st * 8 + o]) * SCALE;
    } else if (o < 16) {
        int i = o - 8;
        float g = gk[st * 8 + i];
        for (int c = 0; c < 64; c++)
            g_Wf[st][o][c] = g * Wk[(st * 8 + i) * 64 + c];
        g_bf[st][o] = g * bk[st * 8 + i] + bek[st * 8 + i];
    } else {
        int i = o - 16;
        for (int c = 0; c < 64; c++)
            g_Wf[st][o][c] = Wv[(st * 64 + i) * 64 + c];
        g_bf[st][o] = bv[st * 64 + i];
    }
}

// ---------------- 2. projections: one stage per CTA (grid 64 x 4), f16 outputs --------
__global__ void __launch_bounds__(128) proj_kernel(const float* __restrict__ x1,
                                                   const float* __restrict__ x2) {
    __shared__ __align__(16) float sW[80][64];
    __shared__ float sb[80];
    int t = threadIdx.x;
    int st = blockIdx.y;

    {
        const float4* src = (const float4*)g_Wf[st];
        float4* dst = (float4*)sW;
#pragma unroll
        for (int i = 0; i < 10; i++) dst[i * 128 + t] = src[i * 128 + t];
        if (t < 80) sb[t] = g_bf[st][t];
    }
    __syncthreads();

    int pos = blockIdx.x * 128 + t;
    int h = pos >> 7, w2 = pos & 127;
    int w = w2 & 63, hv = w2 >> 6;
    const float* xsrc = hv ? x2 : x1;

    float4 xreg[16];
#pragma unroll
    for (int c = 0; c < 16; c++) {
        float4 v;
        v.x = xsrc[(4 * c + 0) * 4096 + h * 64 + w];
        v.y = xsrc[(4 * c + 1) * 4096 + h * 64 + w];
        v.z = xsrc[(4 * c + 2) * 4096 + h * 64 + w];
        v.w = xsrc[(4 * c + 3) * 4096 + h * 64 + w];
        xreg[c] = v;
    }

    int shift = 6 - st;
    int P = 8192 >> (2 * st);
    int m = (1 << shift) - 1;
    int si = h >> shift, hi = h & m;
    int sj = w >> shift, wi = w & m;
    int b = (si << st) + sj;
    int p = (((hi << shift) + wi) << 1) | hv;

    __half* qdst = g_q[st] + b * (8 * P) + p * 8;
    __half* kdst = g_k[st] + b * (8 * P) + p * 8;
#pragma unroll
    for (int o = 0; o < 8; o++) {
        float aq = sb[o], ak = sb[8 + o];
#pragma unroll
        for (int c = 0; c < 16; c++) {
            float4 xv = xreg[c];
            float4 wq = *(const float4*)&sW[o][4 * c];
            float4 wk = *(const float4*)&sW[8 + o][4 * c];
            aq += wq.x * xv.x + wq.y * xv.y + wq.z * xv.z + wq.w * xv.w;
            ak += wk.x * xv.x + wk.y * xv.y + wk.z * xv.z + wk.w * xv.w;
        }
        qdst[o] = __float2half_rn(aq);
        kdst[o] = __float2half_rn(ak);
    }
    __half* vdst = g_v[st] + b * (64 * P) + p;
#pragma unroll 4
    for (int o = 0; o < 64; o += 4) {
        float a0 = sb[16 + o], a1 = sb[17 + o], a2 = sb[18 + o], a3 = sb[19 + o];
#pragma unroll
        for (int c = 0; c < 16; c++) {
            float4 xv = xreg[c];
            float4 w0 = *(const float4*)&sW[16 + o][4 * c];
            float4 w1 = *(const float4*)&sW[17 + o][4 * c];
            float4 w2v = *(const float4*)&sW[18 + o][4 * c];
            float4 w3 = *(const float4*)&sW[19 + o][4 * c];
            a0 += w0.x * xv.x + w0.y * xv.y + w0.z * xv.z + w0.w * xv.w;
            a1 += w1.x * xv.x + w1.y * xv.y + w1.z * xv.z + w1.w * xv.w;
            a2 += w2v.x * xv.x + w2v.y * xv.y + w2v.z * xv.z + w2v.w * xv.w;
            a3 += w3.x * xv.x + w3.y * xv.y + w3.z * xv.z + w3.w * xv.w;
        }
        vdst[(o + 0) * P] = __float2half_rn(a0);
        vdst[(o + 1) * P] = __float2half_rn(a1);
        vdst[(o + 2) * P] = __float2half_rn(a2);
        vdst[(o + 3) * P] = __float2half_rn(a3);
    }
}

// ---------------- 3. flash attention: full fp16 tensor-core, E stays in registers ----------
// grid = 768 CTAs: st0: 512 (qt64 x ks8), st1: 128 (b4 x qt16 x ks2), st2: 64, st3: 64
// (round-13 proven structure: 32-key double-buffered tiles, one barrier per tile)
__global__ void __launch_bounds__(128, 4) flash_kernel() {
    __shared__ __half Vs[2][64][40];   // V tile [c][k], pitch 40 halves
    __shared__ __half Kt[2][32][8];    // K tile [key][ch]

    int bid = blockIdx.x, t = threadIdx.x;
    int st, local, KS, poff;
    if (bid < 512)      { st = 0; local = bid;       KS = 8; poff = 0; }
    else if (bid < 640) { st = 1; local = bid - 512; KS = 2; poff = 8 * 8192; }
    else if (bid < 704) { st = 2; local = bid - 640; KS = 1; poff = 0; }
    else                { st = 3; local = bid - 704; KS = 1; poff = 0; }
    int P = 8192 >> (2 * st);
    int QT = P >> 7;
    int ks = local % KS; local /= KS;
    int qt = local % QT;
    int b = local / QT;
    int Klen = P / KS;
    int k0 = ks * Klen;

    const __half* qbase = g_q[st] + b * (8 * P);
    const __half* kbase = g_k[st] + b * (8 * P);
    const __half* vbase = g_v[st] + b * (64 * P);

    int w = t >> 5, lane = t & 31;
    int g = lane >> 2, r = lane & 3;

    // persistent Q A-fragments (f16, k=8): a0 = row g halves(2r,2r+1), a1 = row g+8
    uint32_t qf[2][2];
#pragma unroll
    for (int mt = 0; mt < 2; mt++) {
        int row = qt * 128 + w * 32 + mt * 16;
        qf[mt][0] = *(const uint32_t*)&qbase[(row + g) * 8 + 2 * r];
        qf[mt][1] = *(const uint32_t*)&qbase[(row + g + 8) * 8 + 2 * r];
    }

    float acc[2][8][4];
#pragma unroll
    for (int mt = 0; mt < 2; mt++)
#pragma unroll
        for (int nt = 0; nt < 8; nt++)
#pragma unroll
            for (int i = 0; i < 4; i++) acc[mt][nt][i] = 0.f;
    float den4[2][2] = {{0.f, 0.f}, {0.f, 0.f}};

    auto stage = [&](int kt, int bi) {
        if (kt < Klen) {
            if (t < 32) {
                *(float4*)&Kt[bi][t][0] = *(const float4*)&kbase[(k0 + kt + t) * 8];
            }
#pragma unroll
            for (int i = 0; i < 2; i++) {
                int idx = t + i * 128;          // 256 chunks of 8 halves
                int c = idx >> 2, j8 = idx & 3;
                *(float4*)&Vs[bi][c][j8 * 8] =
                    *(const float4*)&vbase[c * P + k0 + kt + j8 * 8];
            }
        }
    };

    stage(0, 0);
    __syncthreads();

    int nb = Klen >> 5;
    for (int n = 0; n < nb; n++) {
        int cur = n & 1, nxt = cur ^ 1;
        stage((n + 1) << 5, nxt);   // overlaps both MMA phases

        // phase 1: QK via f16 MMA -> exp -> pack E as f16x2 A-fragments (registers only)
        uint32_t eh[2][4][2];
#pragma unroll
        for (int nt = 0; nt < 4; nt++) {
            uint32_t kb = *(const uint32_t*)&Kt[cur][nt * 8 + g][2 * r];
            float sc0[4] = {0.f, 0.f, 0.f, 0.f};
            float sc1[4] = {0.f, 0.f, 0.f, 0.f};
            mma_h808(sc0, qf[0][0], qf[0][1], kb);
            mma_h808(sc1, qf[1][0], qf[1][1], kb);
            float e00 = ex2(sc0[0]), e01 = ex2(sc0[1]), e02 = ex2(sc0[2]), e03 = ex2(sc0[3]);
            den4[0][0] += e00 + e01;
            den4[0][1] += e02 + e03;
            eh[0][nt][0] = packh2(e00, e01);
            eh[0][nt][1] = packh2(e02, e03);
            float e10 = ex2(sc1[0]), e11 = ex2(sc1[1]), e12 = ex2(sc1[2]), e13 = ex2(sc1[3]);
            den4[1][0] += e10 + e11;
            den4[1][1] += e12 + e13;
            eh[1][nt][0] = packh2(e10, e11);
            eh[1][nt][1] = packh2(e12, e13);
        }

        // phase 2: EV via f16 m16n8k16; A from registers (eh), B from Vs
#pragma unroll
        for (int k16 = 0; k16 < 2; k16++) {
#pragma unroll
            for (int nt = 0; nt < 8; nt++) {
                uint32_t b0 = *(const uint32_t*)&Vs[cur][nt * 8 + g][16 * k16 + 2 * r];
                uint32_t b1 = *(const uint32_t*)&Vs[cur][nt * 8 + g][16 * k16 + 8 + 2 * r];
                mma_h16816(acc[0][nt], eh[0][2 * k16][0], eh[0][2 * k16][1],
                           eh[0][2 * k16 + 1][0], eh[0][2 * k16 + 1][1], b0, b1);
                mma_h16816(acc[1][nt], eh[1][2 * k16][0], eh[1][2 * k16][1],
                           eh[1][2 * k16 + 1][0], eh[1][2 * k16 + 1][1], b0, b1);
            }
        }
        __syncthreads();   // single barrier per tile
    }

    // reduce den across the 4 lanes sharing a row
#pragma unroll
    for (int mt = 0; mt < 2; mt++)
#pragma unroll
        for (int rr = 0; rr < 2; rr++) {
            float d = den4[mt][rr];
            d += __shfl_xor_sync(0xFFFFFFFFu, d, 1);
            d += __shfl_xor_sync(0xFFFFFFFFu, d, 2);
            den4[mt][rr] = d;
        }

    if (KS > 1) {
#pragma unroll
        for (int mt = 0; mt < 2; mt++)
#pragma unroll
            for (int rr = 0; rr < 2; rr++) {
                int qrow = w * 32 + mt * 16 + g + rr * 8;
                int row = poff + ks * 8192 + b * P + qt * 128 + qrow;
                if (r == 0) g_denp[row] = den4[mt][rr];
#pragma unroll
                for (int nt = 0; nt < 8; nt++) {
                    float2 v;
                    v.x = acc[mt][nt][2 * rr];
                    v.y = acc[mt][nt][2 * rr + 1];
                    *(float2*)&g_accp[row][nt * 8 + 2 * r] = v;
                }
            }
    } else {
        int shift = 6 - st;
        int si = b >> st, sj = b & ((1 << st) - 1);
#pragma unroll
        for (int mt = 0; mt < 2; mt++)
#pragma unroll
            for (int rr = 0; rr < 2; rr++) {
                int qrow = w * 32 + mt * 16 + g + rr * 8;
                int p = qt * 128 + qrow;
                float inv = 1.0f / den4[mt][rr];
                int hv = p & 1, tt2 = p >> 1;
                int hi = tt2 >> shift, wi = tt2 & ((1 << shift) - 1);
                int h = (si << shift) + hi;
                int w2 = (sj << shift) + wi + (hv << 6);
                int pos = (h << 7) + w2;
                float* dstp = g_ctx + pos * 256 + st * 64;
#pragma unroll
                for (int nt = 0; nt < 8; nt++) {
                    float2 v;
                    v.x = acc[mt][nt][2 * rr] * inv;
                    v.y = acc[mt][nt][2 * rr + 1] * inv;
                    *(float2*)(dstp + nt * 8 + 2 * r) = v;
                }
            }
    }
}

// ---------------- 4. reduce splits (stages 0,1), normalize, scatter ----------------
// 128 threads = 16 rows x 8 channel-groups of 8; grid (512, 2) — doubled TLP vs r13
__global__ void __launch_bounds__(128) reduce_kernel() {
    int st = blockIdx.y;  // 0 or 1
    int t = threadIdx.x;
    int qi = blockIdx.x * 16 + (t >> 3);
    int cg = t & 7;
    int KS = (st == 0) ? 8 : 2;
    int poff = (st == 0) ? 0 : 8 * 8192;
    int row0 = poff + qi;

    float den = 0.f;
    for (int ksp = 0; ksp < KS; ksp++) den += g_denp[row0 + ksp * 8192];
    float inv = 1.0f / den;

    int shift2 = 13 - 2 * st;
    int Pb = 1 << shift2;
    int b = qi >> shift2, p = qi & (Pb - 1);
    int shift = 6 - st;
    int si = b >> st, sj = b & ((1 << st) - 1);
    int hv = p & 1, tt = p >> 1;
    int hi = tt >> shift, wi = tt & ((1 << shift) - 1);
    int h = (si << shift) + hi;
    int w2 = (sj << shift) + wi + (hv << 6);
    int pos = (h << 7) + w2;

    float* dst = g_ctx + pos * 256 + st * 64 + cg * 8;
#pragma unroll
    for (int c = 0; c < 8; c += 4) {
        float4 s = make_float4(0.f, 0.f, 0.f, 0.f);
        for (int ksp = 0; ksp < KS; ksp++) {
            float4 a = *(const float4*)&g_accp[row0 + ksp * 8192][cg * 8 + c];
            s.x += a.x; s.y += a.y; s.z += a.z; s.w += a.w;
        }
        s.x *= inv; s.y *= inv; s.z *= inv; s.w *= inv;
        *(float4*)(dst + c) = s;
    }
}

// ---------------- 5. final 1x1 conv via tf32 MMA: out[64 x 8192] = Wo[64 x 256] * ctx^T ------
__global__ void __launch_bounds__(128) conv_kernel(const float* __restrict__ Wo,
                                                   float* __restrict__ out) {
    __shared__ float As[64][36];   // ctx tile [pos][k]
    __shared__ float Bs[64][36];   // Wo tile  [o][k]
    int t = threadIdx.x;
    int pos0 = blockIdx.x * 64;
    int w = t >> 5, lane = t & 31;
    int g = lane >> 2, r = lane & 3;

    float acc[4][2][4];
#pragma unroll
    for (int mt = 0; mt < 4; mt++)
#pragma unroll
        for (int nt = 0; nt < 2; nt++)
#pragma unroll
            for (int i = 0; i < 4; i++) acc[mt][nt][i] = 0.f;

    for (int ci0 = 0; ci0 < 256; ci0 += 32) {
        __syncthreads();
#pragma unroll
        for (int i = 0; i < 4; i++) {
            int idx = t + i * 128;
            int a = idx >> 3, j8 = idx & 7;
            float4 v = *(const float4*)&g_ctx[(pos0 + a) * 256 + ci0 + j8 * 4];
            v.x = tf32r(v.x); v.y = tf32r(v.y); v.z = tf32r(v.z); v.w = tf32r(v.w);
            *(float4*)&As[a][j8 * 4] = v;
            float4 u = *(const float4*)&Wo[a * 256 + ci0 + j8 * 4];
            u.x = tf32r(u.x); u.y = tf32r(u.y); u.z = tf32r(u.z); u.w = tf32r(u.w);
            *(float4*)&Bs[a][j8 * 4] = u;
        }
        __syncthreads();

#pragma unroll
        for (int ks8 = 0; ks8 < 4; ks8++) {
            int kk = ks8 * 8;
            uint32_t af[4][4];
#pragma unroll
            for (int mt = 0; mt < 4; mt++) {
                int row = mt * 16;
                af[mt][0] = __float_as_uint(Bs[row + g][kk + r]);
                af[mt][1] = __float_as_uint(Bs[row + g + 8][kk + r]);
                af[mt][2] = __float_as_uint(Bs[row + g][kk + r + 4]);
                af[mt][3] = __float_as_uint(Bs[row + g + 8][kk + r + 4]);
            }
#pragma unroll
            for (int nt = 0; nt < 2; nt++) {
                uint32_t b0 = __float_as_uint(As[w * 16 + nt * 8 + g][kk + r]);
                uint32_t b1 = __float_as_uint(As[w * 16 + nt * 8 + g][kk + r + 4]);
#pragma unroll
                for (int mt = 0; mt < 4; mt++) mma16n8k8(acc[mt][nt], af[mt], b0, b1);
            }
        }
    }

#pragma unroll
    for (int mt = 0; mt < 4; mt++)
#pragma unroll
        for (int rr = 0; rr < 2; rr++) {
            int o = mt * 16 + g + rr * 8;
#pragma unroll
            for (int nt = 0; nt < 2; nt++) {
                int pos = pos0 + w * 16 + nt * 8 + 2 * r;
                int h = pos >> 7, w2 = pos & 127;
                int idx = (w2 < 64) ? (o * 4096 + h * 64 + w2)
                                    : (262144 + o * 4096 + h * 64 + (w2 - 64));
                float2 v;
                v.x = acc[mt][nt][2 * rr];
                v.y = acc[mt][nt][2 * rr + 1];
                *(float2*)&out[idx] = v;
            }
        }
}

// ---------------- launch ----------------
extern "C" void kernel_launch(void* const* d_in, const int* in_sizes, int n_in,
                              void* d_out, int out_size) {
    const float* x1 = (const float*)d_in[0];
    const float* x2 = (const float*)d_in[1];
    const float* Wq = (const float*)d_in[2];
    const float* bq = (const float*)d_in[3];
    const float* gq = (const float*)d_in[4];
    const float* beq = (const float*)d_in[5];
    const float* Wk = (const float*)d_in[6];
    const float* bk = (const float*)d_in[7];
    const float* gk = (const float*)d_in[8];
    const float* bek = (const float*)d_in[9];
    const float* Wv = (const float*)d_in[10];
    const float* bv = (const float*)d_in[11];
    const float* Wo = (const float*)d_in[12];
    float* out = (float*)d_out;

    fold_kernel<<<4, 80>>>(Wq, bq, gq, beq, Wk, bk, gk, bek, Wv, bv);
    proj_kernel<<<dim3(64, 4), 128>>>(x1, x2);
    flash_kernel<<<768, 128>>>();
    reduce_kernel<<<dim3(512, 2), 128>>>();
    conv_kernel<<<128, 128>>>(Wo, out);
}

// round 17
// speedup vs baseline: 1.4734x; 1.0263x over previous
#include <cuda_runtime.h>
#include <cuda_fp16.h>
#include <cstdint>

typedef unsigned long long ull;

// ---------------- static scratch (no allocations allowed) ----------------
__device__ __half g_q[4][8 * 8192];        // [st][ b*8P + p*8 + c ]  POINT-major, scaled, f16
__device__ __half g_k[4][8 * 8192];        // [st][ b*8P + p*8 + c ]  point-major, f16
__device__ __half g_v[4][64 * 8192];       // [st][ b*64P + c*P + p ] channel-major, f16
__device__ float g_accp[10 * 8192][64];    // split-K partial numerators (stages 0,1 only)
__device__ float g_denp[10 * 8192];        // split-K partial denominators
__device__ float g_ctx[8192 * 256];        // [pos][st*64+c]

// ---------------- helpers ----------------
__device__ __forceinline__ float ex2(float x) {
    float y;
    asm("ex2.approx.f32 %0, %1;" : "=f"(y) : "f"(x));
    return y;
}
__device__ __forceinline__ float tf32r(float x) {
    uint32_t u;
    asm("cvt.rna.tf32.f32 %0, %1;" : "=r"(u) : "f"(x));
    return __uint_as_float(u);
}
// pack two f32 into f16x2: lo = first elem (smaller k), hi = second
__device__ __forceinline__ uint32_t packh2(float lo, float hi) {
    uint32_t d;
    asm("cvt.rn.f16x2.f32 %0, %1, %2;" : "=r"(d) : "f"(hi), "f"(lo));
    return d;
}

// tf32 MMA (conv): D(16x8) += A(16x8,row) * B(8x8,col)
__device__ __forceinline__ void mma16n8k8(float* d, const uint32_t* a, uint32_t b0, uint32_t b1) {
    asm volatile(
        "mma.sync.aligned.m16n8k8.row.col.f32.tf32.tf32.f32 "
        "{%0,%1,%2,%3}, {%4,%5,%6,%7}, {%8,%9}, {%0,%1,%2,%3};"
        : "+f"(d[0]), "+f"(d[1]), "+f"(d[2]), "+f"(d[3])
        : "r"(a[0]), "r"(a[1]), "r"(a[2]), "r"(a[3]), "r"(b0), "r"(b1));
}
// f16 MMA k=8: D(16x8) += A(16x8,row,f16) * B(8x8,col,f16)
__device__ __forceinline__ void mma_h808(float* d, uint32_t a0, uint32_t a1, uint32_t b0) {
    asm volatile(
        "mma.sync.aligned.m16n8k8.row.col.f32.f16.f16.f32 "
        "{%0,%1,%2,%3}, {%4,%5}, {%6}, {%0,%1,%2,%3};"
        : "+f"(d[0]), "+f"(d[1]), "+f"(d[2]), "+f"(d[3])
        : "r"(a0), "r"(a1), "r"(b0));
}
// f16 MMA k=16: D(16x8) += A(16x16,row,f16) * B(16x8,col,f16)
__device__ __forceinline__ void mma_h16816(float* d, uint32_t a0, uint32_t a1, uint32_t a2,
                                           uint32_t a3, uint32_t b0, uint32_t b1) {
    asm volatile(
        "mma.sync.aligned.m16n8k16.row.col.f32.f16.f16.f32 "
        "{%0,%1,%2,%3}, {%4,%5,%6,%7}, {%8,%9}, {%0,%1,%2,%3};"
        : "+f"(d[0]), "+f"(d[1]), "+f"(d[2]), "+f"(d[3])
        : "r"(a0), "r"(a1), "r"(a2), "r"(a3), "r"(b0), "r"(b1));
}

// ---------------- 1. projections with INLINE BN-fold: one stage per CTA (grid 64 x 4) ------
__global__ void __launch_bounds__(128) proj_kernel(
    const float* __restrict__ x1, const float* __restrict__ x2,
    const float* __restrict__ Wq, const float* __restrict__ bq,
    const float* __restrict__ gq, const float* __restrict__ beq,
    const float* __restrict__ Wk, const float* __restrict__ bk,
    const float* __restrict__ gk, const float* __restrict__ bek,
    const float* __restrict__ Wv, const float* __restrict__ bv) {
    __shared__ __align__(16) float sW[80][64];
    __shared__ float sb[80];
    int t = threadIdx.x;
    int st = blockIdx.y;
    const float SCALE = 0.35355339059327373f * 1.4426950408889634f;  // kc^-0.5 * log2e

    // fold BN affine + softmax scale while staging weights into smem
#pragma unroll 4
    for (int i = 0; i < 40; i++) {
        int idx = i * 128 + t;          // 0..5119
        int o = idx >> 6, c = idx & 63;
        float v;
        if (o < 8)       v = gq[st * 8 + o] * Wq[(st * 8 + o) * 64 + c] * SCALE;
        else if (o < 16) v = gk[st * 8 + o - 8] * Wk[(st * 8 + o - 8) * 64 + c];
        else             v = Wv[(st * 64 + o - 16) * 64 + c];
        ((float*)sW)[idx] = v;
    }
    if (t < 80) {
        float bvv;
        if (t < 8)       bvv = (gq[st * 8 + t] * bq[st * 8 + t] + beq[st * 8 + t]) * SCALE;
        else if (t < 16) bvv = gk[st * 8 + t - 8] * bk[st * 8 + t - 8] + bek[st * 8 + t - 8];
        else             bvv = bv[st * 64 + t - 16];
        sb[t] = bvv;
    }
    __syncthreads();

    int pos = blockIdx.x * 128 + t;
    int h = pos >> 7, w2 = pos & 127;
    int w = w2 & 63, hv = w2 >> 6;
    const float* xsrc = hv ? x2 : x1;

    float4 xreg[16];
#pragma unroll
    for (int c = 0; c < 16; c++) {
        float4 v;
        v.x = xsrc[(4 * c + 0) * 4096 + h * 64 + w];
        v.y = xsrc[(4 * c + 1) * 4096 + h * 64 + w];
        v.z = xsrc[(4 * c + 2) * 4096 + h * 64 + w];
        v.w = xsrc[(4 * c + 3) * 4096 + h * 64 + w];
        xreg[c] = v;
    }

    int shift = 6 - st;
    int P = 8192 >> (2 * st);
    int m = (1 << shift) - 1;
    int si = h >> shift, hi = h & m;
    int sj = w >> shift, wi = w & m;
    int b = (si << st) + sj;
    int p = (((hi << shift) + wi) << 1) | hv;

    __half* qdst = g_q[st] + b * (8 * P) + p * 8;
    __half* kdst = g_k[st] + b * (8 * P) + p * 8;
#pragma unroll
    for (int o = 0; o < 8; o++) {
        float aq = sb[o], ak = sb[8 + o];
#pragma unroll
        for (int c = 0; c < 16; c++) {
            float4 xv = xreg[c];
            float4 wq = *(const float4*)&sW[o][4 * c];
            float4 wk = *(const float4*)&sW[8 + o][4 * c];
            aq += wq.x * xv.x + wq.y * xv.y + wq.z * xv.z + wq.w * xv.w;
            ak += wk.x * xv.x + wk.y * xv.y + wk.z * xv.z + wk.w * xv.w;
        }
        qdst[o] = __float2half_rn(aq);
        kdst[o] = __float2half_rn(ak);
    }
    __half* vdst = g_v[st] + b * (64 * P) + p;
#pragma unroll 4
    for (int o = 0; o < 64; o += 4) {
        float a0 = sb[16 + o], a1 = sb[17 + o], a2 = sb[18 + o], a3 = sb[19 + o];
#pragma unroll
        for (int c = 0; c < 16; c++) {
            float4 xv = xreg[c];
            float4 w0 = *(const float4*)&sW[16 + o][4 * c];
            float4 w1 = *(const float4*)&sW[17 + o][4 * c];
            float4 w2v = *(const float4*)&sW[18 + o][4 * c];
            float4 w3 = *(const float4*)&sW[19 + o][4 * c];
            a0 += w0.x * xv.x + w0.y * xv.y + w0.z * xv.z + w0.w * xv.w;
            a1 += w1.x * xv.x + w1.y * xv.y + w1.z * xv.z + w1.w * xv.w;
            a2 += w2v.x * xv.x + w2v.y * xv.y + w2v.z * xv.z + w2v.w * xv.w;
            a3 += w3.x * xv.x + w3.y * xv.y + w3.z * xv.z + w3.w * xv.w;
        }
        vdst[(o + 0) * P] = __float2half_rn(a0);
        vdst[(o + 1) * P] = __float2half_rn(a1);
        vdst[(o + 2) * P] = __float2half_rn(a2);
        vdst[(o + 3) * P] = __float2half_rn(a3);
    }
}

// ---------------- 2. flash attention: full fp16 tensor-core, E stays in registers ----------
// grid = 768 CTAs: st0: 512 (qt64 x ks8), st1: 128 (b4 x qt16 x ks2), st2: 64, st3: 64
__global__ void __launch_bounds__(128, 4) flash_kernel() {
    __shared__ __half Vs[2][64][40];   // V tile [c][k], pitch 40 halves
    __shared__ __half Kt[2][32][8];    // K tile [key][ch]

    int bid = blockIdx.x, t = threadIdx.x;
    int st, local, KS, poff;
    if (bid < 512)      { st = 0; local = bid;       KS = 8; poff = 0; }
    else if (bid < 640) { st = 1; local = bid - 512; KS = 2; poff = 8 * 8192; }
    else if (bid < 704) { st = 2; local = bid - 640; KS = 1; poff = 0; }
    else                { st = 3; local = bid - 704; KS = 1; poff = 0; }
    int P = 8192 >> (2 * st);
    int QT = P >> 7;
    int ks = local % KS; local /= KS;
    int qt = local % QT;
    int b = local / QT;
    int Klen = P / KS;
    int k0 = ks * Klen;

    const __half* qbase = g_q[st] + b * (8 * P);
    const __half* kbase = g_k[st] + b * (8 * P);
    const __half* vbase = g_v[st] + b * (64 * P);

    int w = t >> 5, lane = t & 31;
    int g = lane >> 2, r = lane & 3;

    // persistent Q A-fragments (f16, k=8)
    uint32_t qf[2][2];
#pragma unroll
    for (int mt = 0; mt < 2; mt++) {
        int row = qt * 128 + w * 32 + mt * 16;
        qf[mt][0] = *(const uint32_t*)&qbase[(row + g) * 8 + 2 * r];
        qf[mt][1] = *(const uint32_t*)&qbase[(row + g + 8) * 8 + 2 * r];
    }

    float acc[2][8][4];
#pragma unroll
    for (int mt = 0; mt < 2; mt++)
#pragma unroll
        for (int nt = 0; nt < 8; nt++)
#pragma unroll
            for (int i = 0; i < 4; i++) acc[mt][nt][i] = 0.f;
    float den4[2][2] = {{0.f, 0.f}, {0.f, 0.f}};

    auto stage = [&](int kt, int bi) {
        if (kt < Klen) {
            if (t < 32) {
                *(float4*)&Kt[bi][t][0] = *(const float4*)&kbase[(k0 + kt + t) * 8];
            }
#pragma unroll
            for (int i = 0; i < 2; i++) {
                int idx = t + i * 128;          // 256 chunks of 8 halves
                int c = idx >> 2, j8 = idx & 3;
                *(float4*)&Vs[bi][c][j8 * 8] =
                    *(const float4*)&vbase[c * P + k0 + kt + j8 * 8];
            }
        }
    };

    stage(0, 0);
    __syncthreads();

    int nb = Klen >> 5;
    for (int n = 0; n < nb; n++) {
        int cur = n & 1, nxt = cur ^ 1;
        stage((n + 1) << 5, nxt);   // overlaps both MMA phases

        // phase 1: QK via f16 MMA -> exp -> pack E as f16x2 A-fragments (registers only)
        uint32_t eh[2][4][2];
#pragma unroll
        for (int nt = 0; nt < 4; nt++) {
            uint32_t kb = *(const uint32_t*)&Kt[cur][nt * 8 + g][2 * r];
            float sc0[4] = {0.f, 0.f, 0.f, 0.f};
            float sc1[4] = {0.f, 0.f, 0.f, 0.f};
            mma_h808(sc0, qf[0][0], qf[0][1], kb);
            mma_h808(sc1, qf[1][0], qf[1][1], kb);
            float e00 = ex2(sc0[0]), e01 = ex2(sc0[1]), e02 = ex2(sc0[2]), e03 = ex2(sc0[3]);
            den4[0][0] += e00 + e01;
            den4[0][1] += e02 + e03;
            eh[0][nt][0] = packh2(e00, e01);
            eh[0][nt][1] = packh2(e02, e03);
            float e10 = ex2(sc1[0]), e11 = ex2(sc1[1]), e12 = ex2(sc1[2]), e13 = ex2(sc1[3]);
            den4[1][0] += e10 + e11;
            den4[1][1] += e12 + e13;
            eh[1][nt][0] = packh2(e10, e11);
            eh[1][nt][1] = packh2(e12, e13);
        }

        // phase 2: EV via f16 m16n8k16; A from registers (eh), B from Vs
#pragma unroll
        for (int k16 = 0; k16 < 2; k16++) {
#pragma unroll
            for (int nt = 0; nt < 8; nt++) {
                uint32_t b0 = *(const uint32_t*)&Vs[cur][nt * 8 + g][16 * k16 + 2 * r];
                uint32_t b1 = *(const uint32_t*)&Vs[cur][nt * 8 + g][16 * k16 + 8 + 2 * r];
                mma_h16816(acc[0][nt], eh[0][2 * k16][0], eh[0][2 * k16][1],
                           eh[0][2 * k16 + 1][0], eh[0][2 * k16 + 1][1], b0, b1);
                mma_h16816(acc[1][nt], eh[1][2 * k16][0], eh[1][2 * k16][1],
                           eh[1][2 * k16 + 1][0], eh[1][2 * k16 + 1][1], b0, b1);
            }
        }
        __syncthreads();   // single barrier per tile
    }

    // reduce den across the 4 lanes sharing a row
#pragma unroll
    for (int mt = 0; mt < 2; mt++)
#pragma unroll
        for (int rr = 0; rr < 2; rr++) {
            float d = den4[mt][rr];
            d += __shfl_xor_sync(0xFFFFFFFFu, d, 1);
            d += __shfl_xor_sync(0xFFFFFFFFu, d, 2);
            den4[mt][rr] = d;
        }

    if (KS > 1) {
#pragma unroll
        for (int mt = 0; mt < 2; mt++)
#pragma unroll
            for (int rr = 0; rr < 2; rr++) {
                int qrow = w * 32 + mt * 16 + g + rr * 8;
                int row = poff + ks * 8192 + b * P + qt * 128 + qrow;
                if (r == 0) g_denp[row] = den4[mt][rr];
#pragma unroll
                for (int nt = 0; nt < 8; nt++) {
                    float2 v;
                    v.x = acc[mt][nt][2 * rr];
                    v.y = acc[mt][nt][2 * rr + 1];
                    *(float2*)&g_accp[row][nt * 8 + 2 * r] = v;
                }
            }
    } else {
        int shift = 6 - st;
        int si = b >> st, sj = b & ((1 << st) - 1);
#pragma unroll
        for (int mt = 0; mt < 2; mt++)
#pragma unroll
            for (int rr = 0; rr < 2; rr++) {
                int qrow = w * 32 + mt * 16 + g + rr * 8;
                int p = qt * 128 + qrow;
                float inv = 1.0f / den4[mt][rr];
                int hv = p & 1, tt2 = p >> 1;
                int hi = tt2 >> shift, wi = tt2 & ((1 << shift) - 1);
                int h = (si << shift) + hi;
                int w2 = (sj << shift) + wi + (hv << 6);
                int pos = (h << 7) + w2;
                float* dstp = g_ctx + pos * 256 + st * 64;
#pragma unroll
                for (int nt = 0; nt < 8; nt++) {
                    float2 v;
                    v.x = acc[mt][nt][2 * rr] * inv;
                    v.y = acc[mt][nt][2 * rr + 1] * inv;
                    *(float2*)(dstp + nt * 8 + 2 * r) = v;
                }
            }
    }
}

// ---------------- 3. reduce splits (stages 0,1), normalize, scatter ----------------
// 128 threads = 16 rows x 8 channel-groups of 8; grid (512, 2)
__global__ void __launch_bounds__(128) reduce_kernel() {
    int st = blockIdx.y;  // 0 or 1
    int t = threadIdx.x;
    int qi = blockIdx.x * 16 + (t >> 3);
    int cg = t & 7;
    int KS = (st == 0) ? 8 : 2;
    int poff = (st == 0) ? 0 : 8 * 8192;
    int row0 = poff + qi;

    float den = 0.f;
    for (int ksp = 0; ksp < KS; ksp++) den += g_denp[row0 + ksp * 8192];
    float inv = 1.0f / den;

    int shift2 = 13 - 2 * st;
    int Pb = 1 << shift2;
    int b = qi >> shift2, p = qi & (Pb - 1);
    int shift = 6 - st;
    int si = b >> st, sj = b & ((1 << st) - 1);
    int hv = p & 1, tt = p >> 1;
    int hi = tt >> shift, wi = tt & ((1 << shift) - 1);
    int h = (si << shift) + hi;
    int w2 = (sj << shift) + wi + (hv << 6);
    int pos = (h << 7) + w2;

    float* dst = g_ctx + pos * 256 + st * 64 + cg * 8;
#pragma unroll
    for (int c = 0; c < 8; c += 4) {
        float4 s = make_float4(0.f, 0.f, 0.f, 0.f);
        for (int ksp = 0; ksp < KS; ksp++) {
            float4 a = *(const float4*)&g_accp[row0 + ksp * 8192][cg * 8 + c];
            s.x += a.x; s.y += a.y; s.z += a.z; s.w += a.w;
        }
        s.x *= inv; s.y *= inv; s.z *= inv; s.w *= inv;
        *(float4*)(dst + c) = s;
    }
}

// ---------------- 4. final 1x1 conv via tf32 MMA, 256 CTAs x 32 positions ------
__global__ void __launch_bounds__(128) conv_kernel(const float* __restrict__ Wo,
                                                   float* __restrict__ out) {
    __shared__ float As[32][36];   // ctx tile [pos][k]
    __shared__ float Bs[64][36];   // Wo tile  [o][k]
    int t = threadIdx.x;
    int pos0 = blockIdx.x * 32;
    int w = t >> 5, lane = t & 31;
    int g = lane >> 2, r = lane & 3;

    float acc[4][4];
#pragma unroll
    for (int mt = 0; mt < 4; mt++)
#pragma unroll
        for (int i = 0; i < 4; i++) acc[mt][i] = 0.f;

    for (int ci0 = 0; ci0 < 256; ci0 += 32) {
        __syncthreads();
        // As: 32 pos x 32 ch = 256 float4 (2/thread); Bs: 64 o x 32 ch = 512 float4 (4/thread)
#pragma unroll
        for (int i = 0; i < 2; i++) {
            int idx = t + i * 128;
            int a = idx >> 3, j8 = idx & 7;
            float4 v = *(const float4*)&g_ctx[(pos0 + a) * 256 + ci0 + j8 * 4];
            v.x = tf32r(v.x); v.y = tf32r(v.y); v.z = tf32r(v.z); v.w = tf32r(v.w);
            *(float4*)&As[a][j8 * 4] = v;
        }
#pragma unroll
        for (int i = 0; i < 4; i++) {
            int idx = t + i * 128;
            int a = idx >> 3, j8 = idx & 7;
            float4 u = *(const float4*)&Wo[a * 256 + ci0 + j8 * 4];
            u.x = tf32r(u.x); u.y = tf32r(u.y); u.z = tf32r(u.z); u.w = tf32r(u.w);
            *(float4*)&Bs[a][j8 * 4] = u;
        }
        __syncthreads();

#pragma unroll
        for (int ks8 = 0; ks8 < 4; ks8++) {
            int kk = ks8 * 8;
            uint32_t b0 = __float_as_uint(As[w * 8 + g][kk + r]);
            uint32_t b1 = __float_as_uint(As[w * 8 + g][kk + r + 4]);
#pragma unroll
            for (int mt = 0; mt < 4; mt++) {
                int row = mt * 16;
                uint32_t af[4];
                af[0] = __float_as_uint(Bs[row + g][kk + r]);
                af[1] = __float_as_uint(Bs[row + g + 8][kk + r]);
                af[2] = __float_as_uint(Bs[row + g][kk + r + 4]);
                af[3] = __float_as_uint(Bs[row + g + 8][kk + r + 4]);
                mma16n8k8(acc[mt], af, b0, b1);
            }
        }
    }

    // epilogue: C(m=o, n=pos); position pairs contiguous, never cross half boundary
#pragma unroll
    for (int mt = 0; mt < 4; mt++)
#pragma unroll
        for (int rr = 0; rr < 2; rr++) {
            int o = mt * 16 + g + rr * 8;
            int pos = pos0 + w * 8 + 2 * r;
            int h = pos >> 7, w2 = pos & 127;
            int idx = (w2 < 64) ? (o * 4096 + h * 64 + w2)
                                : (262144 + o * 4096 + h * 64 + (w2 - 64));
            float2 v;
            v.x = acc[mt][2 * rr];
            v.y = acc[mt][2 * rr + 1];
            *(float2*)&out[idx] = v;
        }
}

// ---------------- launch ----------------
extern "C" void kernel_launch(void* const* d_in, const int* in_sizes, int n_in,
                              void* d_out, int out_size) {
    const float* x1 = (const float*)d_in[0];
    const float* x2 = (const float*)d_in[1];
    const float* Wq = (const float*)d_in[2];
    const float* bq = (const float*)d_in[3];
    const float* gq = (const float*)d_in[4];
    const float* beq = (const float*)d_in[5];
    const float* Wk = (const float*)d_in[6];
    const float* bk = (const float*)d_in[7];
    const float* gk = (const float*)d_in[8];
    const float* bek = (const float*)d_in[9];
    const float* Wv = (const float*)d_in[10];
    const float* bv = (const float*)d_in[11];
    const float* Wo = (const float*)d_in[12];
    float* out = (float*)d_out;

    proj_kernel<<<dim3(64, 4), 128>>>(x1, x2, Wq, bq, gq, beq, Wk, bk, gk, bek, Wv, bv);
    flash_kernel<<<768, 128>>>();
    reduce_kernel<<<dim3(512, 2), 128>>>();
    conv_kernel<<<256, 128>>>(Wo, out);
}